// round 7
// baseline (speedup 1.0000x reference)
#include <cuda_runtime.h>

#define MM 512
#define NN 512
#define NPIX (MM*NN)

typedef unsigned long long u64;

__device__ float2 g_base[NPIX];   // {Xb, yb}
__device__ float2 g_det[NPIX];    // {Xd, yd - Xd}
__device__ unsigned g_bmin[1024], g_bmax[1024];

#define LOG2E 1.4426950408889634f

#define FMA2(d,a,b,c) asm("fma.rn.f32x2 %0, %1, %2, %3;" : "=l"(d) : "l"(a), "l"(b), "l"(c))
#define ADD2(d,a,b)   asm("add.rn.f32x2 %0, %1, %2;"     : "=l"(d) : "l"(a), "l"(b))
#define MUL2(d,a,b)   asm("mul.rn.f32x2 %0, %1, %2;"     : "=l"(d) : "l"(a), "l"(b))
#define PACK2(d,lo,hi) asm("mov.b64 %0, {%1, %2};" : "=l"(d) : "f"(lo), "f"(hi))
#define UNPACK2(lo,hi,s) asm("mov.b64 {%0, %1}, %2;" : "=f"(lo), "=f"(hi) : "l"(s))
__device__ __forceinline__ float ex2f(float a) {
    float r; asm("ex2.approx.f32 %0, %1;" : "=f"(r) : "f"(a)); return r;
}

__device__ __forceinline__ unsigned f2key(float f) {
    unsigned u = __float_as_uint(f);
    return (u & 0x80000000u) ? ~u : (u | 0x80000000u);
}
__device__ __forceinline__ float key2f(unsigned k) {
    unsigned u = (k & 0x80000000u) ? (k ^ 0x80000000u) : ~k;
    return __uint_as_float(u);
}

// ---- fused: 9x9 box (zero pad, /81) + detail + per-block y min/max ----
__global__ __launch_bounds__(256) void k_pre(const float* __restrict__ X,
                                             const float* __restrict__ Y) {
    __shared__ float2 raw[16][40];
    __shared__ float2 hs[16][32];
    __shared__ unsigned smn[8], smx[8];

    int tx = threadIdx.x, ty = threadIdx.y;
    int bx = blockIdx.x * 32, by = blockIdx.y * 8;
    int tid = ty * 32 + tx;

    for (int k = tid; k < 16 * 40; k += 256) {
        int r = k / 40, c = k % 40;
        int gi = by + r - 4, gj = bx + c - 4;
        float2 v = make_float2(0.f, 0.f);
        if ((unsigned)gi < 512u && (unsigned)gj < 512u) {
            int idx = (gi << 9) + gj;
            v = make_float2(X[idx], Y[idx]);
        }
        raw[r][c] = v;
    }
    __syncthreads();

    for (int k = tid; k < 16 * 32; k += 256) {
        int r = k >> 5, c = k & 31;
        float sx = 0.f, sy = 0.f;
        #pragma unroll
        for (int d = 0; d < 9; ++d) {
            float2 v = raw[r][c + d];
            sx += v.x; sy += v.y;
        }
        hs[r][c] = make_float2(sx, sy);
    }
    __syncthreads();

    float sx = 0.f, sy = 0.f;
    #pragma unroll
    for (int d = 0; d < 9; ++d) {
        float2 v = hs[ty + d][tx];
        sx += v.x; sy += v.y;
    }
    const float inv81 = 1.0f / 81.0f;
    float xb = sx * inv81, yb = sy * inv81;
    float2 ctr = raw[ty + 4][tx + 4];
    float xd = ctr.x - xb;
    float zd = (ctr.y - yb) - xd;
    int idx = ((by + ty) << 9) + bx + tx;
    g_base[idx] = make_float2(xb, yb);
    g_det[idx]  = make_float2(xd, zd);

    // block min/max of y
    unsigned key = f2key(ctr.y);
    unsigned mn = key, mx = key;
    #pragma unroll
    for (int o = 16; o; o >>= 1) {
        mn = min(mn, __shfl_xor_sync(0xFFFFFFFFu, mn, o));
        mx = max(mx, __shfl_xor_sync(0xFFFFFFFFu, mx, o));
    }
    if ((tid & 31) == 0) { smn[tid >> 5] = mn; smx[tid >> 5] = mx; }
    __syncthreads();
    if (tid == 0) {
        unsigned m = smn[0], M = smx[0];
        #pragma unroll
        for (int w = 1; w < 8; ++w) { m = min(m, smn[w]); M = max(M, smx[w]); }
        int bid = blockIdx.y * 16 + blockIdx.x;
        g_bmin[bid] = m;
        g_bmax[bid] = M;
    }
}

// ================= main bilateral kernel =================
// Block 32x4 threads, tile 64 cols x 8 rows: thread handles 4 pixels —
// 2 center rows (gi0, gi0+1) x 2 lane columns (j0, j0+32).
// f32x2 lanes = the two columns; window-row loads shared by both centers.
// Shared tiles: II[r][c] = {v[bx+c-H], v[bx+c-H+32]}.
#define TB_ROWS 26   // 8 + 2*9
#define TB_COLS 50   // 32 + 2*9
#define TD_ROWS 12   // 8 + 2*2
#define TD_COLS 40   // 32 + 2*4

__global__ __launch_bounds__(128) void k_main(const float* __restrict__ R,
                                              float* __restrict__ out) {
    __shared__ float2 bXs[TB_ROWS][TB_COLS];
    __shared__ float2 bYs[TB_ROWS][TB_COLS];
    __shared__ float2 dXs[TD_ROWS][TD_COLS];
    __shared__ float2 dYs[TD_ROWS][TD_COLS];
    __shared__ unsigned smn[4], smx[4];

    int tx = threadIdx.x, ty = threadIdx.y;   // 32 x 4
    int bx = blockIdx.x * 64, by = blockIdx.y * 8;
    int tid = ty * 32 + tx;

    // global min/max reduction (per-block partials from k_pre)
    {
        unsigned mn = 0xFFFFFFFFu, mx = 0u;
        #pragma unroll
        for (int i = 0; i < 8; ++i) {
            int k = tid + 128 * i;
            mn = min(mn, g_bmin[k]);
            mx = max(mx, g_bmax[k]);
        }
        #pragma unroll
        for (int o = 16; o; o >>= 1) {
            mn = min(mn, __shfl_xor_sync(0xFFFFFFFFu, mn, o));
            mx = max(mx, __shfl_xor_sync(0xFFFFFFFFu, mx, o));
        }
        if ((tid & 31) == 0) { smn[tid >> 5] = mn; smx[tid >> 5] = mx; }
    }

    for (int k = tid; k < TB_ROWS * TB_COLS; k += 128) {
        int r = k / TB_COLS, c = k % TB_COLS;
        int gi = min(max(by + r - 9, 0), 511);
        int ga = min(max(bx + c - 9, 0), 511);
        int gb = min(max(bx + c + 23, 0), 511);
        float2 v0 = g_base[(gi << 9) + ga];
        float2 v1 = g_base[(gi << 9) + gb];
        bXs[r][c] = make_float2(v0.x, v1.x);
        bYs[r][c] = make_float2(v0.y, v1.y);
    }
    for (int k = tid; k < TD_ROWS * TD_COLS; k += 128) {
        int r = k / TD_COLS, c = k % TD_COLS;
        int gi = min(max(by + r - 2, 0), 511);
        int ga = min(max(bx + c - 4, 0), 511);
        int gb = min(max(bx + c + 28, 0), 511);
        float2 v0 = g_det[(gi << 9) + ga];
        float2 v1 = g_det[(gi << 9) + gb];
        dXs[r][c] = make_float2(v0.x, v1.x);
        dYs[r][c] = make_float2(v0.y, v1.y);
    }
    __syncthreads();

    float Cs;
    {
        unsigned m = min(min(smn[0], smn[1]), min(smn[2], smn[3]));
        unsigned M = max(max(smx[0], smx[1]), max(smx[2], smx[3]));
        float sigma = R[0] * (key2f(M) - key2f(m));
        float h = sigma * 0.5f;
        Cs = -LOG2E / (h * h);
    }
    u64 C2; PACK2(C2, Cs, Cs);

    const float invS1L = LOG2E / 8145.0625f;   // (19*19/4)^2
    const float invS0L = LOG2E / 126.5625f;    // (5*9/4)^2

    int ty2 = 2 * ty;
    int gi0 = by + ty2;               // center rows gi0, gi0+1
    int j0 = bx + tx, j1 = j0 + 32;

    // per-lane chunk windows
    int kc0 = min((j0 - 1) / 62, 8), kc1 = min((j1 - 1) / 62, 8);
    int cs0 = 62 * kc0, ce0 = min(cs0 + 64, 512);
    int cs1 = 62 * kc1, ce1 = min(cs1 + 64, 512);

    // ---------------- Base: 19x19, 2 centers x 2 lanes ----------------
    float2 c0v = bXs[ty2 + 9][tx + 9];
    float2 c1v = bXs[ty2 + 10][tx + 9];
    u64 nx0, nx1;
    { float a = -c0v.x, b = -c0v.y; PACK2(nx0, a, b); }
    { float a = -c1v.x, b = -c1v.y; PACK2(nx1, a, b); }

    u64 Lb[19];
    {
        #pragma unroll
        for (int dj = 0; dj < 19; ++dj) {
            int cc = dj - 9;
            float s = -(float)(cc * cc) * invS1L;
            int ja = j0 - 9 + dj, jb = j1 - 9 + dj;
            float l0 = (ja >= cs0 && ja < ce0) ? s : -1e30f;
            float l1 = (jb >= cs1 && jb < ce1) ? s : -1e30f;
            PACK2(Lb[dj], l0, l1);
        }
    }

    u64 g0 = 0, g1 = 0, g2 = 0, g3 = 0, g4 = 0;   // center0
    u64 h0 = 0, h1 = 0, h2 = 0, h3 = 0, h4 = 0;   // center1

    #pragma unroll 1
    for (int r = 0; r < 20; ++r) {
        bool rok = (unsigned)(gi0 + r - 9) < 512u;   // same abs row for both centers
        int d0 = r - 9, d1 = r - 10;
        float e0 = (r <= 18 && rok) ? ex2f(-(float)(d0 * d0) * invS1L) : 0.f;
        float e1 = (r >= 1 && rok) ? ex2f(-(float)(d1 * d1) * invS1L) : 0.f;

        const u64* rx = (const u64*)&bXs[ty2 + r][tx];
        const u64* ry = (const u64*)&bYs[ty2 + r][tx];

        u64 p0 = 0, p1 = 0, p2 = 0, p3 = 0, p4 = 0;
        u64 q0 = 0, q1 = 0, q2 = 0, q3 = 0, q4 = 0;
        #pragma unroll
        for (int dj = 0; dj < 19; ++dj) {
            u64 vx = rx[dj];
            u64 vy = ry[dj];
            // center 0
            {
                u64 d, t, a;
                ADD2(d, vx, nx0);
                MUL2(t, d, C2);
                FMA2(a, t, d, Lb[dj]);
                float a0, a1; UNPACK2(a0, a1, a);
                float w0 = ex2f(a0), w1 = ex2f(a1);
                u64 w; PACK2(w, w0, w1);
                ADD2(p0, p0, w);
                u64 wx; MUL2(wx, w, vx);
                ADD2(p1, p1, wx);
                FMA2(p2, wx, vx, p2);
                FMA2(p3, w, vy, p3);
                FMA2(p4, wx, vy, p4);
            }
            // center 1
            {
                u64 d, t, a;
                ADD2(d, vx, nx1);
                MUL2(t, d, C2);
                FMA2(a, t, d, Lb[dj]);
                float a0, a1; UNPACK2(a0, a1, a);
                float w0 = ex2f(a0), w1 = ex2f(a1);
                u64 w; PACK2(w, w0, w1);
                ADD2(q0, q0, w);
                u64 wx; MUL2(wx, w, vx);
                ADD2(q1, q1, wx);
                FMA2(q2, wx, vx, q2);
                FMA2(q3, w, vy, q3);
                FMA2(q4, wx, vy, q4);
            }
        }
        u64 e02; PACK2(e02, e0, e0);
        u64 e12; PACK2(e12, e1, e1);
        FMA2(g0, e02, p0, g0); FMA2(g1, e02, p1, g1); FMA2(g2, e02, p2, g2);
        FMA2(g3, e02, p3, g3); FMA2(g4, e02, p4, g4);
        FMA2(h0, e12, q0, h0); FMA2(h1, e12, q1, h1); FMA2(h2, e12, q2, h2);
        FMA2(h3, e12, q3, h3); FMA2(h4, e12, q4, h4);
    }

    float A00, B00, A01, B01, A10, B10, A11, B11;  // A{center}{lane}
    {
        float sw0, sw1, sx0, sx1, sxx0, sxx1, sy0, sy1, sxy0, sxy1;
        UNPACK2(sw0, sw1, g0); UNPACK2(sx0, sx1, g1); UNPACK2(sxx0, sxx1, g2);
        UNPACK2(sy0, sy1, g3); UNPACK2(sxy0, sxy1, g4);
        {
            float inv = 1.0f / sw0;
            float mx = sx0 * inv, my = sy0 * inv;
            float var = fmaf(-mx, mx, sxx0 * inv);
            float cov = fmaf(-mx, my, sxy0 * inv);
            A00 = cov / (var + 1e-6f); B00 = fmaf(-A00, mx, my);
        }
        {
            float inv = 1.0f / sw1;
            float mx = sx1 * inv, my = sy1 * inv;
            float var = fmaf(-mx, mx, sxx1 * inv);
            float cov = fmaf(-mx, my, sxy1 * inv);
            A01 = cov / (var + 1e-6f); B01 = fmaf(-A01, mx, my);
        }
    }
    {
        float sw0, sw1, sx0, sx1, sxx0, sxx1, sy0, sy1, sxy0, sxy1;
        UNPACK2(sw0, sw1, h0); UNPACK2(sx0, sx1, h1); UNPACK2(sxx0, sxx1, h2);
        UNPACK2(sy0, sy1, h3); UNPACK2(sxy0, sxy1, h4);
        {
            float inv = 1.0f / sw0;
            float mx = sx0 * inv, my = sy0 * inv;
            float var = fmaf(-mx, mx, sxx0 * inv);
            float cov = fmaf(-mx, my, sxy0 * inv);
            A10 = cov / (var + 1e-6f); B10 = fmaf(-A10, mx, my);
        }
        {
            float inv = 1.0f / sw1;
            float mx = sx1 * inv, my = sy1 * inv;
            float var = fmaf(-mx, mx, sxx1 * inv);
            float cov = fmaf(-mx, my, sxy1 * inv);
            A11 = cov / (var + 1e-6f); B11 = fmaf(-A11, mx, my);
        }
    }

    // ---------------- Detail: 5x9, 2 centers x 2 lanes ----------------
    float2 d0v = dXs[ty2 + 2][tx + 4];
    float2 d1v = dXs[ty2 + 3][tx + 4];
    u64 nd0, nd1;
    { float a = -d0v.x, b = -d0v.y; PACK2(nd0, a, b); }
    { float a = -d1v.x, b = -d1v.y; PACK2(nd1, a, b); }

    u64 Ld[9];
    {
        #pragma unroll
        for (int dj = 0; dj < 9; ++dj) {
            int cc = dj - 4;
            float s = -(float)(cc * cc) * invS0L;
            int ja = j0 - 4 + dj, jb = j1 - 4 + dj;
            float l0 = (ja >= cs0 && ja < ce0) ? s : -1e30f;
            float l1 = (jb >= cs1 && jb < ce1) ? s : -1e30f;
            PACK2(Ld[dj], l0, l1);
        }
    }

    u64 s00 = 0, s01 = 0, s10 = 0, s11 = 0;   // {center}{w|wz}
    #pragma unroll
    for (int r = 0; r < 6; ++r) {
        bool rok = (unsigned)(gi0 + r - 2) < 512u;
        int d0 = r - 2, d1 = r - 3;
        float e0 = (r <= 4 && rok) ? ex2f(-(float)(d0 * d0) * invS0L) : 0.f;
        float e1 = (r >= 1 && rok) ? ex2f(-(float)(d1 * d1) * invS0L) : 0.f;

        const u64* rx = (const u64*)&dXs[ty2 + r][tx];
        const u64* ry = (const u64*)&dYs[ty2 + r][tx];
        u64 p0 = 0, p1 = 0, q0 = 0, q1 = 0;
        #pragma unroll
        for (int dj = 0; dj < 9; ++dj) {
            u64 vx = rx[dj];
            u64 vy = ry[dj];
            {
                u64 d, t, a;
                ADD2(d, vx, nd0);
                MUL2(t, d, C2);
                FMA2(a, t, d, Ld[dj]);
                float a0, a1; UNPACK2(a0, a1, a);
                float w0 = ex2f(a0), w1 = ex2f(a1);
                u64 w; PACK2(w, w0, w1);
                ADD2(p0, p0, w);
                FMA2(p1, w, vy, p1);
            }
            {
                u64 d, t, a;
                ADD2(d, vx, nd1);
                MUL2(t, d, C2);
                FMA2(a, t, d, Ld[dj]);
                float a0, a1; UNPACK2(a0, a1, a);
                float w0 = ex2f(a0), w1 = ex2f(a1);
                u64 w; PACK2(w, w0, w1);
                ADD2(q0, q0, w);
                FMA2(q1, w, vy, q1);
            }
        }
        u64 e02; PACK2(e02, e0, e0);
        u64 e12; PACK2(e12, e1, e1);
        FMA2(s00, e02, p0, s00);
        FMA2(s01, e02, p1, s01);
        FMA2(s10, e12, q0, s10);
        FMA2(s11, e12, q1, s11);
    }

    float sw00, sw01, sz00, sz01, sw10, sw11, sz10, sz11;
    UNPACK2(sw00, sw01, s00);
    UNPACK2(sz00, sz01, s01);
    UNPACK2(sw10, sw11, s10);
    UNPACK2(sz10, sz11, s11);

    int o0 = (gi0 << 9);
    out[o0 + j0]       = fmaf(A00, c0v.x, B00 + d0v.x + sz00 / sw00);
    out[o0 + j1]       = fmaf(A01, c0v.y, B01 + d0v.y + sz01 / sw01);
    out[o0 + 512 + j0] = fmaf(A10, c1v.x, B10 + d1v.x + sz10 / sw10);
    out[o0 + 512 + j1] = fmaf(A11, c1v.y, B11 + d1v.y + sz11 / sw11);
}

extern "C" void kernel_launch(void* const* d_in, const int* in_sizes, int n_in,
                              void* d_out, int out_size) {
    const float* X = (const float*)d_in[0];
    const float* Y = (const float*)d_in[1];
    const float* R = (const float*)d_in[2];
    float* out = (float*)d_out;

    k_pre<<<dim3(16, 64), dim3(32, 8)>>>(X, Y);
    k_main<<<dim3(8, 64), dim3(32, 4)>>>(R, out);
}

// round 8
// speedup vs baseline: 1.0972x; 1.0972x over previous
#include <cuda_runtime.h>

#define MM 512
#define NN 512
#define NPIX (MM*NN)

typedef unsigned long long u64;

__device__ float2 g_base[NPIX];   // {Xb, yb}
__device__ float2 g_det[NPIX];    // {Xd, yd - Xd}
__device__ unsigned g_bmin[1024], g_bmax[1024];

#define LOG2E 1.4426950408889634f

#define FMA2(d,a,b,c) asm("fma.rn.f32x2 %0, %1, %2, %3;" : "=l"(d) : "l"(a), "l"(b), "l"(c))
#define ADD2(d,a,b)   asm("add.rn.f32x2 %0, %1, %2;"     : "=l"(d) : "l"(a), "l"(b))
#define MUL2(d,a,b)   asm("mul.rn.f32x2 %0, %1, %2;"     : "=l"(d) : "l"(a), "l"(b))
#define PACK2(d,lo,hi) asm("mov.b64 %0, {%1, %2};" : "=l"(d) : "f"(lo), "f"(hi))
#define UNPACK2(lo,hi,s) asm("mov.b64 {%0, %1}, %2;" : "=f"(lo), "=f"(hi) : "l"(s))
__device__ __forceinline__ float ex2f(float a) {
    float r; asm("ex2.approx.f32 %0, %1;" : "=f"(r) : "f"(a)); return r;
}

__device__ __forceinline__ unsigned f2key(float f) {
    unsigned u = __float_as_uint(f);
    return (u & 0x80000000u) ? ~u : (u | 0x80000000u);
}
__device__ __forceinline__ float key2f(unsigned k) {
    unsigned u = (k & 0x80000000u) ? (k ^ 0x80000000u) : ~k;
    return __uint_as_float(u);
}

// ---- fused: 9x9 box (zero pad, /81) + detail + per-block y min/max ----
__global__ __launch_bounds__(256) void k_pre(const float* __restrict__ X,
                                             const float* __restrict__ Y) {
    __shared__ float2 raw[16][40];
    __shared__ float2 hs[16][32];
    __shared__ unsigned smn[8], smx[8];

    int tx = threadIdx.x, ty = threadIdx.y;
    int bx = blockIdx.x * 32, by = blockIdx.y * 8;
    int tid = ty * 32 + tx;

    for (int k = tid; k < 16 * 40; k += 256) {
        int r = k / 40, c = k % 40;
        int gi = by + r - 4, gj = bx + c - 4;
        float2 v = make_float2(0.f, 0.f);
        if ((unsigned)gi < 512u && (unsigned)gj < 512u) {
            int idx = (gi << 9) + gj;
            v = make_float2(X[idx], Y[idx]);
        }
        raw[r][c] = v;
    }
    __syncthreads();

    for (int k = tid; k < 16 * 32; k += 256) {
        int r = k >> 5, c = k & 31;
        float sx = 0.f, sy = 0.f;
        #pragma unroll
        for (int d = 0; d < 9; ++d) {
            float2 v = raw[r][c + d];
            sx += v.x; sy += v.y;
        }
        hs[r][c] = make_float2(sx, sy);
    }
    __syncthreads();

    float sx = 0.f, sy = 0.f;
    #pragma unroll
    for (int d = 0; d < 9; ++d) {
        float2 v = hs[ty + d][tx];
        sx += v.x; sy += v.y;
    }
    const float inv81 = 1.0f / 81.0f;
    float xb = sx * inv81, yb = sy * inv81;
    float2 ctr = raw[ty + 4][tx + 4];
    float xd = ctr.x - xb;
    float zd = (ctr.y - yb) - xd;
    int idx = ((by + ty) << 9) + bx + tx;
    g_base[idx] = make_float2(xb, yb);
    g_det[idx]  = make_float2(xd, zd);

    unsigned key = f2key(ctr.y);
    unsigned mn = key, mx = key;
    #pragma unroll
    for (int o = 16; o; o >>= 1) {
        mn = min(mn, __shfl_xor_sync(0xFFFFFFFFu, mn, o));
        mx = max(mx, __shfl_xor_sync(0xFFFFFFFFu, mx, o));
    }
    if ((tid & 31) == 0) { smn[tid >> 5] = mn; smx[tid >> 5] = mx; }
    __syncthreads();
    if (tid == 0) {
        unsigned m = smn[0], M = smx[0];
        #pragma unroll
        for (int w = 1; w < 8; ++w) { m = min(m, smn[w]); M = max(M, smx[w]); }
        int bid = blockIdx.y * 16 + blockIdx.x;
        g_bmin[bid] = m;
        g_bmax[bid] = M;
    }
}

// ================= main bilateral kernel (R5 structure) =================
// Tile: 32 cols x 8 rows. Block: 32x4 threads, 2 output rows per thread.
// Shared arrays hold OVERLAPPING PAIRS: s[r][c] = {v[c], v[c+1]}.
// Consumers read pairs at STRIDE 2: row[2p] = {v[tx+2p], v[tx+2p+1]}.
#define TROW 26      // 8 + 2*9
#define TCOL 51      // 32 + 2*9 + 1
#define DROW 12      // 8 + 2*2
#define DCOL 41      // 32 + 2*4 + 1

__global__ __launch_bounds__(128, 6) void k_main(const float* __restrict__ R,
                                                 float* __restrict__ out) {
    __shared__ float2 sbx[TROW][TCOL];
    __shared__ float2 sby[TROW][TCOL];
    __shared__ float2 sdx[DROW][DCOL];
    __shared__ float2 sdy[DROW][DCOL];
    __shared__ unsigned smn[4], smx[4];

    int tx = threadIdx.x, ty = threadIdx.y;
    int bx = blockIdx.x * 32, by = blockIdx.y * 8;
    int tid = ty * 32 + tx;

    // global min/max reduction from k_pre partials
    {
        unsigned mn = 0xFFFFFFFFu, mx = 0u;
        #pragma unroll
        for (int i = 0; i < 8; ++i) {
            int k = tid + 128 * i;
            mn = min(mn, g_bmin[k]);
            mx = max(mx, g_bmax[k]);
        }
        #pragma unroll
        for (int o = 16; o; o >>= 1) {
            mn = min(mn, __shfl_xor_sync(0xFFFFFFFFu, mn, o));
            mx = max(mx, __shfl_xor_sync(0xFFFFFFFFu, mx, o));
        }
        if ((tid & 31) == 0) { smn[tid >> 5] = mn; smx[tid >> 5] = mx; }
    }

    // Fill: value at (r,c) goes to [c].x and [c-1].y (overlapping pairs)
    for (int k = tid; k < TROW * TCOL; k += 128) {
        int r = k / TCOL, c = k % TCOL;
        int gi = min(max(by + r - 9, 0), 511);
        int gj = min(max(bx + c - 9, 0), 511);
        float2 v = g_base[(gi << 9) + gj];
        sbx[r][c].x = v.x;
        sby[r][c].x = v.y;
        if (c > 0) { sbx[r][c - 1].y = v.x; sby[r][c - 1].y = v.y; }
    }
    for (int k = tid; k < DROW * DCOL; k += 128) {
        int r = k / DCOL, c = k % DCOL;
        int gi = min(max(by + r - 2, 0), 511);
        int gj = min(max(bx + c - 4, 0), 511);
        float2 v = g_det[(gi << 9) + gj];
        sdx[r][c].x = v.x;
        sdy[r][c].x = v.y;
        if (c > 0) { sdx[r][c - 1].y = v.x; sdy[r][c - 1].y = v.y; }
    }
    __syncthreads();

    float Cs;
    {
        unsigned m = min(min(smn[0], smn[1]), min(smn[2], smn[3]));
        unsigned M = max(max(smx[0], smx[1]), max(smx[2], smx[3]));
        float sigma = R[0] * (key2f(M) - key2f(m));
        float h = sigma * 0.5f;
        Cs = -LOG2E / (h * h);
    }
    u64 C2; PACK2(C2, Cs, Cs);

    int ty2 = ty * 2;
    int gi0 = by + ty2;          // center 0 row; center 1 = gi0+1
    int gj  = bx + tx;

    // chunk window
    int kch = (gj - 1) / 62;
    kch = min(kch, 8);
    int cs = 62 * kch;
    int ce = min(cs + 64, 512);

    const float invS1L = LOG2E / 8145.0625f;   // (19*19/4)^2
    const float invS0L = LOG2E / 126.5625f;    // (5*9/4)^2

    // ---------------- Base: 19x19, two centers ----------------
    float xc0 = sbx[ty2 + 9][tx + 9].x;
    float xc1 = sbx[ty2 + 10][tx + 9].x;
    u64 nx0, nx1;
    { float a = -xc0; PACK2(nx0, a, a); }
    { float a = -xc1; PACK2(nx1, a, a); }

    u64 Lb[10];
    {
        #pragma unroll
        for (int p = 0; p < 10; ++p) {
            float l0 = -1e30f, l1 = -1e30f;
            int dj0 = 2 * p, dj1 = 2 * p + 1;
            int j0 = gj - 9 + dj0, j1 = gj - 9 + dj1;
            if (j0 >= cs && j0 < ce) { int cc = dj0 - 9; l0 = -(float)(cc * cc) * invS1L; }
            if (dj1 < 19 && j1 >= cs && j1 < ce) { int cc = dj1 - 9; l1 = -(float)(cc * cc) * invS1L; }
            PACK2(Lb[p], l0, l1);
        }
    }

    u64 g0 = 0, g1 = 0, g2 = 0, g3 = 0, g4 = 0;      // center0: w, wx, wxx, wy, wxy
    u64 h0 = 0, h1 = 0, h2 = 0, h3 = 0, h4 = 0;      // center1

    #pragma unroll 1
    for (int r = 0; r < 20; ++r) {
        bool rowok = (unsigned)(gi0 + r - 9) < 512u;
        int d0 = r - 9, d1 = r - 10;
        float e0 = (r <= 18 && rowok) ? ex2f(-(float)(d0 * d0) * invS1L) : 0.f;
        float e1 = (r >= 1 && rowok) ? ex2f(-(float)(d1 * d1) * invS1L) : 0.f;

        const u64* rbx = (const u64*)&sbx[ty2 + r][tx];
        const u64* rby = (const u64*)&sby[ty2 + r][tx];

        u64 p0 = 0, p1 = 0, p2 = 0, p3 = 0, p4 = 0;
        u64 q0 = 0, q1 = 0, q2 = 0, q3 = 0, q4 = 0;
        #pragma unroll
        for (int p = 0; p < 10; ++p) {
            u64 vx2 = rbx[2 * p];
            u64 vy2 = rby[2 * p];
            // center 0
            {
                u64 dd, t, a;
                ADD2(dd, vx2, nx0);
                MUL2(t, dd, C2);
                FMA2(a, t, dd, Lb[p]);
                float a0, a1; UNPACK2(a0, a1, a);
                float w0 = ex2f(a0), w1 = ex2f(a1);
                u64 w; PACK2(w, w0, w1);
                ADD2(p0, p0, w);
                u64 wx; MUL2(wx, w, vx2);
                ADD2(p1, p1, wx);
                FMA2(p2, wx, vx2, p2);
                FMA2(p3, w, vy2, p3);
                FMA2(p4, wx, vy2, p4);
            }
            // center 1
            {
                u64 dd, t, a;
                ADD2(dd, vx2, nx1);
                MUL2(t, dd, C2);
                FMA2(a, t, dd, Lb[p]);
                float a0, a1; UNPACK2(a0, a1, a);
                float w0 = ex2f(a0), w1 = ex2f(a1);
                u64 w; PACK2(w, w0, w1);
                ADD2(q0, q0, w);
                u64 wx; MUL2(wx, w, vx2);
                ADD2(q1, q1, wx);
                FMA2(q2, wx, vx2, q2);
                FMA2(q3, w, vy2, q3);
                FMA2(q4, wx, vy2, q4);
            }
        }
        u64 e02; PACK2(e02, e0, e0);
        u64 e12; PACK2(e12, e1, e1);
        FMA2(g0, e02, p0, g0); FMA2(g1, e02, p1, g1); FMA2(g2, e02, p2, g2);
        FMA2(g3, e02, p3, g3); FMA2(g4, e02, p4, g4);
        FMA2(h0, e12, q0, h0); FMA2(h1, e12, q1, h1); FMA2(h2, e12, q2, h2);
        FMA2(h3, e12, q3, h3); FMA2(h4, e12, q4, h4);
    }

    float A0, B0, A1, B1;
    {
        float a, b, sw, swx, swxx, swy, swxy;
        UNPACK2(a, b, g0); sw = a + b;
        UNPACK2(a, b, g1); swx = a + b;
        UNPACK2(a, b, g2); swxx = a + b;
        UNPACK2(a, b, g3); swy = a + b;
        UNPACK2(a, b, g4); swxy = a + b;
        float invsw = 1.0f / sw;
        float mx = swx * invsw, my = swy * invsw;
        float var = fmaf(-mx, mx, swxx * invsw);
        float cov = fmaf(-mx, my, swxy * invsw);
        A0 = cov / (var + 1e-6f);
        B0 = fmaf(-A0, mx, my);
    }
    {
        float a, b, sw, swx, swxx, swy, swxy;
        UNPACK2(a, b, h0); sw = a + b;
        UNPACK2(a, b, h1); swx = a + b;
        UNPACK2(a, b, h2); swxx = a + b;
        UNPACK2(a, b, h3); swy = a + b;
        UNPACK2(a, b, h4); swxy = a + b;
        float invsw = 1.0f / sw;
        float mx = swx * invsw, my = swy * invsw;
        float var = fmaf(-mx, mx, swxx * invsw);
        float cov = fmaf(-mx, my, swxy * invsw);
        A1 = cov / (var + 1e-6f);
        B1 = fmaf(-A1, mx, my);
    }

    // ---------------- Detail: 5x9, two centers ----------------
    u64 Ld[5];
    {
        #pragma unroll
        for (int p = 0; p < 5; ++p) {
            float l0 = -1e30f, l1 = -1e30f;
            int dj0 = 2 * p, dj1 = 2 * p + 1;
            int j0 = gj - 4 + dj0, j1 = gj - 4 + dj1;
            if (j0 >= cs && j0 < ce) { int cc = dj0 - 4; l0 = -(float)(cc * cc) * invS0L; }
            if (dj1 < 9 && j1 >= cs && j1 < ce) { int cc = dj1 - 4; l1 = -(float)(cc * cc) * invS0L; }
            PACK2(Ld[p], l0, l1);
        }
    }

    float bd[2], xd[2];
    #pragma unroll
    for (int c = 0; c < 2; ++c) {
        float xdc = sdx[ty2 + 2 + c][tx + 4].x;
        xd[c] = xdc;
        u64 nxd; { float a = -xdc; PACK2(nxd, a, a); }
        u64 s0 = 0, s1 = 0;
        #pragma unroll
        for (int di = 0; di < 5; ++di) {
            int dd = di - 2;
            float elr = ((unsigned)(gi0 + c + dd) < 512u) ? ex2f(-(float)(dd * dd) * invS0L) : 0.f;
            const u64* rdx = (const u64*)&sdx[ty2 + c + di][tx];
            const u64* rdy = (const u64*)&sdy[ty2 + c + di][tx];
            u64 r0 = 0, r1 = 0;
            #pragma unroll
            for (int p = 0; p < 5; ++p) {
                u64 vx2 = rdx[2 * p];
                u64 vy2 = rdy[2 * p];
                u64 dv, t, a;
                ADD2(dv, vx2, nxd);
                MUL2(t, dv, C2);
                FMA2(a, t, dv, Ld[p]);
                float a0, a1; UNPACK2(a0, a1, a);
                float w0 = ex2f(a0), w1 = ex2f(a1);
                u64 w; PACK2(w, w0, w1);
                ADD2(r0, r0, w);
                FMA2(r1, w, vy2, r1);
            }
            u64 e2; PACK2(e2, elr, elr);
            FMA2(s0, e2, r0, s0);
            FMA2(s1, e2, r1, s1);
        }
        float a, b, swd, swdz;
        UNPACK2(a, b, s0); swd = a + b;
        UNPACK2(a, b, s1); swdz = a + b;
        bd[c] = swdz / swd;
    }

    out[(gi0 << 9) + gj]       = fmaf(A0, xc0, B0 + xd[0] + bd[0]);
    out[((gi0 + 1) << 9) + gj] = fmaf(A1, xc1, B1 + xd[1] + bd[1]);
}

extern "C" void kernel_launch(void* const* d_in, const int* in_sizes, int n_in,
                              void* d_out, int out_size) {
    const float* X = (const float*)d_in[0];
    const float* Y = (const float*)d_in[1];
    const float* R = (const float*)d_in[2];
    float* out = (float*)d_out;

    k_pre<<<dim3(16, 64), dim3(32, 8)>>>(X, Y);
    k_main<<<dim3(16, 64), dim3(32, 4)>>>(R, out);
}

// round 9
// speedup vs baseline: 1.2882x; 1.1741x over previous
#include <cuda_runtime.h>

#define MM 512
#define NN 512
#define NPIX (MM*NN)

typedef unsigned long long u64;

__device__ float2 g_base[NPIX];   // {Xb, yb}
__device__ float2 g_det[NPIX];    // {Xd, yd - Xd}
__device__ unsigned g_bmin[1024], g_bmax[1024];

#define LOG2E 1.4426950408889634f

#define FMA2(d,a,b,c) asm("fma.rn.f32x2 %0, %1, %2, %3;" : "=l"(d) : "l"(a), "l"(b), "l"(c))
#define ADD2(d,a,b)   asm("add.rn.f32x2 %0, %1, %2;"     : "=l"(d) : "l"(a), "l"(b))
#define MUL2(d,a,b)   asm("mul.rn.f32x2 %0, %1, %2;"     : "=l"(d) : "l"(a), "l"(b))
#define PACK2(d,lo,hi) asm("mov.b64 %0, {%1, %2};" : "=l"(d) : "f"(lo), "f"(hi))
#define UNPACK2(lo,hi,s) asm("mov.b64 {%0, %1}, %2;" : "=f"(lo), "=f"(hi) : "l"(s))
__device__ __forceinline__ float ex2f(float a) {
    float r; asm("ex2.approx.f32 %0, %1;" : "=f"(r) : "f"(a)); return r;
}

__device__ __forceinline__ unsigned f2key(float f) {
    unsigned u = __float_as_uint(f);
    return (u & 0x80000000u) ? ~u : (u | 0x80000000u);
}
__device__ __forceinline__ float key2f(unsigned k) {
    unsigned u = (k & 0x80000000u) ? (k ^ 0x80000000u) : ~k;
    return __uint_as_float(u);
}

// ---- fused: 9x9 box (zero pad, /81) + detail + per-block y min/max ----
__global__ __launch_bounds__(256) void k_pre(const float* __restrict__ X,
                                             const float* __restrict__ Y) {
    __shared__ float2 raw[16][40];
    __shared__ float2 hs[16][32];
    __shared__ unsigned smn[8], smx[8];

    int tx = threadIdx.x, ty = threadIdx.y;
    int bx = blockIdx.x * 32, by = blockIdx.y * 8;
    int tid = ty * 32 + tx;

    for (int k = tid; k < 16 * 40; k += 256) {
        int r = k / 40, c = k % 40;
        int gi = by + r - 4, gj = bx + c - 4;
        float2 v = make_float2(0.f, 0.f);
        if ((unsigned)gi < 512u && (unsigned)gj < 512u) {
            int idx = (gi << 9) + gj;
            v = make_float2(X[idx], Y[idx]);
        }
        raw[r][c] = v;
    }
    __syncthreads();

    for (int k = tid; k < 16 * 32; k += 256) {
        int r = k >> 5, c = k & 31;
        float sx = 0.f, sy = 0.f;
        #pragma unroll
        for (int d = 0; d < 9; ++d) {
            float2 v = raw[r][c + d];
            sx += v.x; sy += v.y;
        }
        hs[r][c] = make_float2(sx, sy);
    }
    __syncthreads();

    float sx = 0.f, sy = 0.f;
    #pragma unroll
    for (int d = 0; d < 9; ++d) {
        float2 v = hs[ty + d][tx];
        sx += v.x; sy += v.y;
    }
    const float inv81 = 1.0f / 81.0f;
    float xb = sx * inv81, yb = sy * inv81;
    float2 ctr = raw[ty + 4][tx + 4];
    float xd = ctr.x - xb;
    float zd = (ctr.y - yb) - xd;
    int idx = ((by + ty) << 9) + bx + tx;
    g_base[idx] = make_float2(xb, yb);
    g_det[idx]  = make_float2(xd, zd);

    unsigned key = f2key(ctr.y);
    unsigned mn = key, mx = key;
    #pragma unroll
    for (int o = 16; o; o >>= 1) {
        mn = min(mn, __shfl_xor_sync(0xFFFFFFFFu, mn, o));
        mx = max(mx, __shfl_xor_sync(0xFFFFFFFFu, mx, o));
    }
    if ((tid & 31) == 0) { smn[tid >> 5] = mn; smx[tid >> 5] = mx; }
    __syncthreads();
    if (tid == 0) {
        unsigned m = smn[0], M = smx[0];
        #pragma unroll
        for (int w = 1; w < 8; ++w) { m = min(m, smn[w]); M = max(M, smx[w]); }
        int bid = blockIdx.y * 16 + blockIdx.x;
        g_bmin[bid] = m;
        g_bmax[bid] = M;
    }
}

// ================= main bilateral kernel =================
// Tile 32 cols x 8 rows, block 32x4, 2 center rows per thread.
// Overlapping-pair smem: s[r][c] = {v[c], v[c+1]}; consumer stride-2 LDS.64.
// Row spatial folded into exponent; invalid rows carry sentinel x=1e19 -> w=0.
#define TROW 26      // 8 + 2*9
#define TCOL 51      // 32 + 2*9 + 1
#define DROW 12      // 8 + 2*2
#define DCOL 41      // 32 + 2*4 + 1

__global__ __launch_bounds__(128, 7) void k_main(const float* __restrict__ R,
                                                 float* __restrict__ out) {
    __shared__ float2 sbx[TROW][TCOL];
    __shared__ float2 sby[TROW][TCOL];
    __shared__ float2 sdx[DROW][DCOL];
    __shared__ float2 sdy[DROW][DCOL];
    __shared__ unsigned smn[4], smx[4];

    int tx = threadIdx.x, ty = threadIdx.y;
    int bx = blockIdx.x * 32, by = blockIdx.y * 8;
    int tid = ty * 32 + tx;

    // global min/max reduction from k_pre partials
    {
        unsigned mn = 0xFFFFFFFFu, mx = 0u;
        #pragma unroll
        for (int i = 0; i < 8; ++i) {
            int k = tid + 128 * i;
            mn = min(mn, g_bmin[k]);
            mx = max(mx, g_bmax[k]);
        }
        #pragma unroll
        for (int o = 16; o; o >>= 1) {
            mn = min(mn, __shfl_xor_sync(0xFFFFFFFFu, mn, o));
            mx = max(mx, __shfl_xor_sync(0xFFFFFFFFu, mx, o));
        }
        if ((tid & 31) == 0) { smn[tid >> 5] = mn; smx[tid >> 5] = mx; }
    }

    // Tile fill; out-of-range rows get sentinel x=1e19 (=> w=0), y=0
    for (int k = tid; k < TROW * TCOL; k += 128) {
        int r = k / TCOL, c = k % TCOL;
        int gi = by + r - 9;
        int gj = min(max(bx + c - 9, 0), 511);
        float vx = 1e19f, vy = 0.f;
        if ((unsigned)gi < 512u) {
            float2 v = g_base[(gi << 9) + gj];
            vx = v.x; vy = v.y;
        }
        sbx[r][c].x = vx;
        sby[r][c].x = vy;
        if (c > 0) { sbx[r][c - 1].y = vx; sby[r][c - 1].y = vy; }
    }
    for (int k = tid; k < DROW * DCOL; k += 128) {
        int r = k / DCOL, c = k % DCOL;
        int gi = by + r - 2;
        int gj = min(max(bx + c - 4, 0), 511);
        float vx = 1e19f, vy = 0.f;
        if ((unsigned)gi < 512u) {
            float2 v = g_det[(gi << 9) + gj];
            vx = v.x; vy = v.y;
        }
        sdx[r][c].x = vx;
        sdy[r][c].x = vy;
        if (c > 0) { sdx[r][c - 1].y = vx; sdy[r][c - 1].y = vy; }
    }
    __syncthreads();

    float Cs;
    {
        unsigned m = min(min(smn[0], smn[1]), min(smn[2], smn[3]));
        unsigned M = max(max(smx[0], smx[1]), max(smx[2], smx[3]));
        float sigma = R[0] * (key2f(M) - key2f(m));
        float h = sigma * 0.5f;
        Cs = -LOG2E / (h * h);
    }
    u64 C2; PACK2(C2, Cs, Cs);

    int ty2 = ty * 2;
    int gi0 = by + ty2;          // center rows gi0, gi0+1
    int gj  = bx + tx;

    // chunk window
    int kch = min((gj - 1) / 62, 8);
    int cs = 62 * kch;
    int ce = min(cs + 64, 512);

    const float invS1L = LOG2E / 8145.0625f;   // (19*19/4)^2
    const float invS0L = LOG2E / 126.5625f;    // (5*9/4)^2

    // ---------------- Base: 19x19, two centers ----------------
    float xc0 = sbx[ty2 + 9][tx + 9].x;
    float xc1 = sbx[ty2 + 10][tx + 9].x;
    u64 nx0, nx1;
    { float a = -xc0; PACK2(nx0, a, a); }
    { float a = -xc1; PACK2(nx1, a, a); }

    u64 Lb[10];
    {
        #pragma unroll
        for (int p = 0; p < 10; ++p) {
            float l0 = -1e30f, l1 = -1e30f;
            int dj0 = 2 * p, dj1 = 2 * p + 1;
            int j0 = gj - 9 + dj0, j1 = gj - 9 + dj1;
            if (j0 >= cs && j0 < ce) { int cc = dj0 - 9; l0 = -(float)(cc * cc) * invS1L; }
            if (dj1 < 19 && j1 >= cs && j1 < ce) { int cc = dj1 - 9; l1 = -(float)(cc * cc) * invS1L; }
            PACK2(Lb[p], l0, l1);
        }
    }

    u64 g0 = 0, g1 = 0, g2 = 0, g3 = 0, g4 = 0;      // center0: w, wx, wxx, wy, wxy
    u64 h0 = 0, h1 = 0, h2 = 0, h3 = 0, h4 = 0;      // center1

    #pragma unroll 1
    for (int r = 0; r < 20; ++r) {
        float fd0 = (float)(r - 9), fd1 = (float)(r - 10);
        float lr0 = (r <= 18) ? -fd0 * fd0 * invS1L : -1e30f;
        float lr1 = (r >= 1)  ? -fd1 * fd1 * invS1L : -1e30f;
        u64 lr02; PACK2(lr02, lr0, lr0);
        u64 lr12; PACK2(lr12, lr1, lr1);

        const u64* rbx = (const u64*)&sbx[ty2 + r][tx];
        const u64* rby = (const u64*)&sby[ty2 + r][tx];

        #pragma unroll
        for (int p = 0; p < 10; ++p) {
            u64 vx2 = rbx[2 * p];
            u64 vy2 = rby[2 * p];
            // center 0
            {
                u64 dd, t, a;
                ADD2(dd, vx2, nx0);
                MUL2(t, dd, C2);
                FMA2(a, t, dd, Lb[p]);
                ADD2(a, a, lr02);
                float a0, a1; UNPACK2(a0, a1, a);
                float w0 = ex2f(a0), w1 = ex2f(a1);
                u64 w; PACK2(w, w0, w1);
                ADD2(g0, g0, w);
                u64 wx; MUL2(wx, w, vx2);
                ADD2(g1, g1, wx);
                FMA2(g2, wx, vx2, g2);
                FMA2(g3, w, vy2, g3);
                FMA2(g4, wx, vy2, g4);
            }
            // center 1
            {
                u64 dd, t, a;
                ADD2(dd, vx2, nx1);
                MUL2(t, dd, C2);
                FMA2(a, t, dd, Lb[p]);
                ADD2(a, a, lr12);
                float a0, a1; UNPACK2(a0, a1, a);
                float w0 = ex2f(a0), w1 = ex2f(a1);
                u64 w; PACK2(w, w0, w1);
                ADD2(h0, h0, w);
                u64 wx; MUL2(wx, w, vx2);
                ADD2(h1, h1, wx);
                FMA2(h2, wx, vx2, h2);
                FMA2(h3, w, vy2, h3);
                FMA2(h4, wx, vy2, h4);
            }
        }
    }

    float A0, B0, A1, B1;
    {
        float a, b, sw, swx, swxx, swy, swxy;
        UNPACK2(a, b, g0); sw = a + b;
        UNPACK2(a, b, g1); swx = a + b;
        UNPACK2(a, b, g2); swxx = a + b;
        UNPACK2(a, b, g3); swy = a + b;
        UNPACK2(a, b, g4); swxy = a + b;
        float invsw = 1.0f / sw;
        float mx = swx * invsw, my = swy * invsw;
        float var = fmaf(-mx, mx, swxx * invsw);
        float cov = fmaf(-mx, my, swxy * invsw);
        A0 = cov / (var + 1e-6f);
        B0 = fmaf(-A0, mx, my);
    }
    {
        float a, b, sw, swx, swxx, swy, swxy;
        UNPACK2(a, b, h0); sw = a + b;
        UNPACK2(a, b, h1); swx = a + b;
        UNPACK2(a, b, h2); swxx = a + b;
        UNPACK2(a, b, h3); swy = a + b;
        UNPACK2(a, b, h4); swxy = a + b;
        float invsw = 1.0f / sw;
        float mx = swx * invsw, my = swy * invsw;
        float var = fmaf(-mx, mx, swxx * invsw);
        float cov = fmaf(-mx, my, swxy * invsw);
        A1 = cov / (var + 1e-6f);
        B1 = fmaf(-A1, mx, my);
    }

    // ---------------- Detail: 5x9, two centers, shared row loads ----------------
    u64 Ld[5];
    {
        #pragma unroll
        for (int p = 0; p < 5; ++p) {
            float l0 = -1e30f, l1 = -1e30f;
            int dj0 = 2 * p, dj1 = 2 * p + 1;
            int j0 = gj - 4 + dj0, j1 = gj - 4 + dj1;
            if (j0 >= cs && j0 < ce) { int cc = dj0 - 4; l0 = -(float)(cc * cc) * invS0L; }
            if (dj1 < 9 && j1 >= cs && j1 < ce) { int cc = dj1 - 4; l1 = -(float)(cc * cc) * invS0L; }
            PACK2(Ld[p], l0, l1);
        }
    }

    float xd0 = sdx[ty2 + 2][tx + 4].x;
    float xd1 = sdx[ty2 + 3][tx + 4].x;
    u64 nd0, nd1;
    { float a = -xd0; PACK2(nd0, a, a); }
    { float a = -xd1; PACK2(nd1, a, a); }

    u64 s00 = 0, s01 = 0, s10 = 0, s11 = 0;   // {center}{w|wz}
    #pragma unroll
    for (int r = 0; r < 6; ++r) {
        float fd0 = (float)(r - 2), fd1 = (float)(r - 3);
        float lr0 = (r <= 4) ? -fd0 * fd0 * invS0L : -1e30f;
        float lr1 = (r >= 1) ? -fd1 * fd1 * invS0L : -1e30f;
        u64 lr02; PACK2(lr02, lr0, lr0);
        u64 lr12; PACK2(lr12, lr1, lr1);

        const u64* rdx = (const u64*)&sdx[ty2 + r][tx];
        const u64* rdy = (const u64*)&sdy[ty2 + r][tx];
        #pragma unroll
        for (int p = 0; p < 5; ++p) {
            u64 vx2 = rdx[2 * p];
            u64 vy2 = rdy[2 * p];
            {
                u64 dv, t, a;
                ADD2(dv, vx2, nd0);
                MUL2(t, dv, C2);
                FMA2(a, t, dv, Ld[p]);
                ADD2(a, a, lr02);
                float a0, a1; UNPACK2(a0, a1, a);
                float w0 = ex2f(a0), w1 = ex2f(a1);
                u64 w; PACK2(w, w0, w1);
                ADD2(s00, s00, w);
                FMA2(s01, w, vy2, s01);
            }
            {
                u64 dv, t, a;
                ADD2(dv, vx2, nd1);
                MUL2(t, dv, C2);
                FMA2(a, t, dv, Ld[p]);
                ADD2(a, a, lr12);
                float a0, a1; UNPACK2(a0, a1, a);
                float w0 = ex2f(a0), w1 = ex2f(a1);
                u64 w; PACK2(w, w0, w1);
                ADD2(s10, s10, w);
                FMA2(s11, w, vy2, s11);
            }
        }
    }

    float a, b, sw0, sz0, sw1, sz1;
    UNPACK2(a, b, s00); sw0 = a + b;
    UNPACK2(a, b, s01); sz0 = a + b;
    UNPACK2(a, b, s10); sw1 = a + b;
    UNPACK2(a, b, s11); sz1 = a + b;

    out[(gi0 << 9) + gj]       = fmaf(A0, xc0, B0 + xd0 + sz0 / sw0);
    out[((gi0 + 1) << 9) + gj] = fmaf(A1, xc1, B1 + xd1 + sz1 / sw1);
}

extern "C" void kernel_launch(void* const* d_in, const int* in_sizes, int n_in,
                              void* d_out, int out_size) {
    const float* X = (const float*)d_in[0];
    const float* Y = (const float*)d_in[1];
    const float* R = (const float*)d_in[2];
    float* out = (float*)d_out;

    k_pre<<<dim3(16, 64), dim3(32, 8)>>>(X, Y);
    k_main<<<dim3(16, 64), dim3(32, 4)>>>(R, out);
}